// round 1
// baseline (speedup 1.0000x reference)
#include <cuda_runtime.h>

#define D      1024
#define NHEAD  16
#define HDIM   64
#define BATCH  4
#define SEQ    2048
#define MTOT   (BATCH*SEQ)   // 8192

// scratch (allocation-free rule: __device__ globals)
__device__ float g_q[(size_t)MTOT * D];
__device__ float g_k[(size_t)MTOT * D];
__device__ float g_v[(size_t)MTOT * D];
__device__ float g_ctx[(size_t)MTOT * D];

// ---------------------------------------------------------------------------
// SGEMM: C[MTOT x D] = A[MTOT x D] @ W[D x D] (+ bias)
// 128x128 tile, BK=8, 256 threads, 8x8 per-thread register tile.
// ---------------------------------------------------------------------------
__device__ __forceinline__ void sgemm_body(const float* __restrict__ A,
                                           const float* __restrict__ W,
                                           float* __restrict__ C,
                                           const float* __restrict__ bias)
{
    __shared__ float As[8][128];   // transposed A tile: As[k][m]
    __shared__ float Bs[8][128];   // Bs[k][n]

    const int tid = threadIdx.x;
    const int tx  = tid & 15;
    const int ty  = tid >> 4;
    const int m0  = blockIdx.y * 128;
    const int n0  = blockIdx.x * 128;

    const int arow = tid >> 1;          // 0..127
    const int acol = (tid & 1) * 4;     // 0 or 4
    const int brow = tid >> 5;          // 0..7
    const int bcol = (tid & 31) * 4;    // 0..124

    const float* Ap = A + (size_t)(m0 + arow) * D + acol;
    const float* Wp = W + (size_t)brow * D + n0 + bcol;

    float acc[8][8];
#pragma unroll
    for (int i = 0; i < 8; i++)
#pragma unroll
        for (int j = 0; j < 8; j++) acc[i][j] = 0.f;

    for (int k0 = 0; k0 < D; k0 += 8) {
        float4 av = *(const float4*)Ap; Ap += 8;
        float4 bv = *(const float4*)Wp; Wp += (size_t)8 * D;

        __syncthreads();   // protect previous iteration's reads
        As[acol + 0][arow] = av.x;
        As[acol + 1][arow] = av.y;
        As[acol + 2][arow] = av.z;
        As[acol + 3][arow] = av.w;
        *(float4*)&Bs[brow][bcol] = bv;
        __syncthreads();

#pragma unroll
        for (int k = 0; k < 8; k++) {
            float4 a0 = *(const float4*)&As[k][ty * 8];
            float4 a1 = *(const float4*)&As[k][ty * 8 + 4];
            float4 b0 = *(const float4*)&Bs[k][tx * 8];
            float4 b1 = *(const float4*)&Bs[k][tx * 8 + 4];
            float a[8] = {a0.x, a0.y, a0.z, a0.w, a1.x, a1.y, a1.z, a1.w};
            float b[8] = {b0.x, b0.y, b0.z, b0.w, b1.x, b1.y, b1.z, b1.w};
#pragma unroll
            for (int i = 0; i < 8; i++)
#pragma unroll
                for (int j = 0; j < 8; j++)
                    acc[i][j] = fmaf(a[i], b[j], acc[i][j]);
        }
    }

#pragma unroll
    for (int i = 0; i < 8; i++) {
        float* crow = C + (size_t)(m0 + ty * 8 + i) * D + n0 + tx * 8;
#pragma unroll
        for (int j = 0; j < 8; j += 4) {
            float4 v;
            v.x = acc[i][j];     v.y = acc[i][j + 1];
            v.z = acc[i][j + 2]; v.w = acc[i][j + 3];
            if (bias) {
                const float* bp = bias + n0 + tx * 8 + j;
                v.x += bp[0]; v.y += bp[1]; v.z += bp[2]; v.w += bp[3];
            }
            *(float4*)(crow + j) = v;
        }
    }
}

__global__ void __launch_bounds__(256) qkv_gemm(const float* __restrict__ x,
                                                const float* __restrict__ Wq,
                                                const float* __restrict__ Wk,
                                                const float* __restrict__ Wv)
{
    const float* W = (blockIdx.z == 0) ? Wq : (blockIdx.z == 1) ? Wk : Wv;
    float* C       = (blockIdx.z == 0) ? g_q : (blockIdx.z == 1) ? g_k : g_v;
    sgemm_body(x, W, C, nullptr);
}

__global__ void __launch_bounds__(256) out_gemm(const float* __restrict__ Wo,
                                                const float* __restrict__ bo,
                                                float* __restrict__ out)
{
    sgemm_body(g_ctx, Wo, out, bo);
}

// ---------------------------------------------------------------------------
// Flash-style causal attention.
// One CTA per (b, h, 64-row query tile). 256 threads (16x16), 4x4 per thread.
// smem: Q tile (64x64) + K^T tile (reused as P tile) + V tile = 48 KB exactly.
// ---------------------------------------------------------------------------
__global__ void __launch_bounds__(256) attn_kernel()
{
    const int mt = blockIdx.x;   // query tile   0..31
    const int h  = blockIdx.y;   // head         0..15
    const int b  = blockIdx.z;   // batch        0..3
    const int m0 = mt * 64;

    __shared__ float Qs[64][64];
    __shared__ float KP[64][64];   // K^T (d-major) first, then reused as P
    __shared__ float Vs[64][64];

    const int tid = threadIdx.x;
    const int tx  = tid & 15;
    const int ty  = tid >> 4;

    // fold 1/sqrt(64) and log2(e) into Q so softmax uses exp2
    const float qscale = 0.125f * 1.4426950408889634f;

    // ---- load Q tile (scaled) ----
    {
        int row = tid >> 2;            // 0..63
        int cb  = (tid & 3) * 4;       // float4-chunk base: 0,4,8,12
        const float* qp = g_q + (size_t)(b * SEQ + m0 + row) * D + h * HDIM;
        float* qs = &Qs[row][0];
#pragma unroll
        for (int cc = 0; cc < 4; cc++) {
            float4 v = *(const float4*)(qp + (cb + cc) * 4);
            v.x *= qscale; v.y *= qscale; v.z *= qscale; v.w *= qscale;
            *(float4*)(qs + (cb + cc) * 4) = v;
        }
    }

    float m_i[4], l_i[4], o[4][4];
#pragma unroll
    for (int i = 0; i < 4; i++) {
        m_i[i] = -1e30f; l_i[i] = 0.f;
#pragma unroll
        for (int j = 0; j < 4; j++) o[i][j] = 0.f;
    }

    for (int kt = 0; kt <= mt; kt++) {
        const int n0 = kt * 64;

        __syncthreads();   // previous PV reads done before overwriting KP/Vs
        // ---- load K^T and V tiles ----
        {
            int col = tid & 63;
            int cb  = (tid >> 6) * 4;
            const float* kp = g_k + (size_t)(b * SEQ + n0 + col) * D + h * HDIM;
#pragma unroll
            for (int cc = 0; cc < 4; cc++) {
                float4 v = *(const float4*)(kp + (cb + cc) * 4);
                int d = (cb + cc) * 4;
                KP[d + 0][col] = v.x; KP[d + 1][col] = v.y;
                KP[d + 2][col] = v.z; KP[d + 3][col] = v.w;
            }
            int row = tid >> 2;
            int cb2 = (tid & 3) * 4;
            const float* vp = g_v + (size_t)(b * SEQ + n0 + row) * D + h * HDIM;
#pragma unroll
            for (int cc = 0; cc < 4; cc++)
                *(float4*)&Vs[row][(cb2 + cc) * 4] = *(const float4*)(vp + (cb2 + cc) * 4);
        }
        __syncthreads();

        // ---- S = Q @ K^T (per-thread 4x4) ----
        float s[4][4];
#pragma unroll
        for (int i = 0; i < 4; i++)
#pragma unroll
            for (int j = 0; j < 4; j++) s[i][j] = 0.f;

#pragma unroll
        for (int d0 = 0; d0 < 64; d0 += 4) {
            float4 qv[4];
#pragma unroll
            for (int i = 0; i < 4; i++) qv[i] = *(const float4*)&Qs[ty * 4 + i][d0];
#pragma unroll
            for (int dd = 0; dd < 4; dd++) {
                float4 kv = *(const float4*)&KP[d0 + dd][tx * 4];
#pragma unroll
                for (int i = 0; i < 4; i++) {
                    float qa = (dd == 0) ? qv[i].x : (dd == 1) ? qv[i].y
                             : (dd == 2) ? qv[i].z : qv[i].w;
                    s[i][0] = fmaf(qa, kv.x, s[i][0]);
                    s[i][1] = fmaf(qa, kv.y, s[i][1]);
                    s[i][2] = fmaf(qa, kv.z, s[i][2]);
                    s[i][3] = fmaf(qa, kv.w, s[i][3]);
                }
            }
        }

        // causal mask on the diagonal tile
        if (kt == mt) {
#pragma unroll
            for (int i = 0; i < 4; i++) {
                int r = ty * 4 + i;
#pragma unroll
                for (int j = 0; j < 4; j++)
                    if (tx * 4 + j > r) s[i][j] = -1e30f;
            }
        }

        __syncthreads();   // done reading KP; about to overwrite with P

        // ---- online softmax + store P ----
#pragma unroll
        for (int i = 0; i < 4; i++) {
            float tm = fmaxf(fmaxf(s[i][0], s[i][1]), fmaxf(s[i][2], s[i][3]));
#pragma unroll
            for (int off = 8; off >= 1; off >>= 1)
                tm = fmaxf(tm, __shfl_xor_sync(0xffffffffu, tm, off));
            float mn    = fmaxf(m_i[i], tm);
            float alpha = exp2f(m_i[i] - mn);
            float rs = 0.f;
#pragma unroll
            for (int j = 0; j < 4; j++) {
                s[i][j] = exp2f(s[i][j] - mn);
                rs += s[i][j];
            }
#pragma unroll
            for (int off = 8; off >= 1; off >>= 1)
                rs += __shfl_xor_sync(0xffffffffu, rs, off);
            l_i[i] = l_i[i] * alpha + rs;
            m_i[i] = mn;
#pragma unroll
            for (int j = 0; j < 4; j++) o[i][j] *= alpha;
            *(float4*)&KP[ty * 4 + i][tx * 4] =
                make_float4(s[i][0], s[i][1], s[i][2], s[i][3]);
        }
        __syncthreads();

        // ---- O += P @ V ----
#pragma unroll
        for (int c0 = 0; c0 < 64; c0 += 4) {
            float4 pv[4];
#pragma unroll
            for (int i = 0; i < 4; i++) pv[i] = *(const float4*)&KP[ty * 4 + i][c0];
#pragma unroll
            for (int dd = 0; dd < 4; dd++) {
                float4 vv = *(const float4*)&Vs[c0 + dd][tx * 4];
#pragma unroll
                for (int i = 0; i < 4; i++) {
                    float pa = (dd == 0) ? pv[i].x : (dd == 1) ? pv[i].y
                             : (dd == 2) ? pv[i].z : pv[i].w;
                    o[i][0] = fmaf(pa, vv.x, o[i][0]);
                    o[i][1] = fmaf(pa, vv.y, o[i][1]);
                    o[i][2] = fmaf(pa, vv.z, o[i][2]);
                    o[i][3] = fmaf(pa, vv.w, o[i][3]);
                }
            }
        }
    }

    // ---- write ctx (b, n, h*hd layout -> contiguous (8192, 1024)) ----
#pragma unroll
    for (int i = 0; i < 4; i++) {
        float inv = 1.f / l_i[i];
        float* cp = g_ctx + (size_t)(b * SEQ + m0 + ty * 4 + i) * D + h * HDIM + tx * 4;
        *(float4*)cp = make_float4(o[i][0] * inv, o[i][1] * inv,
                                   o[i][2] * inv, o[i][3] * inv);
    }
}

// ---------------------------------------------------------------------------
extern "C" void kernel_launch(void* const* d_in, const int* in_sizes, int n_in,
                              void* d_out, int out_size)
{
    const float* x  = (const float*)d_in[0];
    const float* Wq = (const float*)d_in[1];
    const float* Wk = (const float*)d_in[2];
    const float* Wv = (const float*)d_in[3];
    const float* Wo = (const float*)d_in[4];
    const float* bo = (const float*)d_in[5];
    float* out = (float*)d_out;

    qkv_gemm<<<dim3(D / 128, MTOT / 128, 3), 256>>>(x, Wq, Wk, Wv);
    attn_kernel<<<dim3(SEQ / 64, NHEAD, BATCH), 256>>>();
    out_gemm<<<dim3(D / 128, MTOT / 128, 1), 256>>>(Wo, bo, out);
}

// round 3
// speedup vs baseline: 3.3733x; 3.3733x over previous
#include <cuda_runtime.h>
#include <cuda_bf16.h>
#include <cuda_fp16.h>
#include <cstdint>

#define D      1024
#define NHEAD  16
#define HDIM   64
#define BATCH  4
#define SEQ    2048
#define MTOT   (BATCH*SEQ)   // 8192

// ---------------- scratch (__device__ globals; no allocation allowed) ------
__device__ float g_ctx[(size_t)MTOT * D];

__device__ __nv_bfloat16 g_xh[(size_t)MTOT * D];
__device__ __nv_bfloat16 g_xl[(size_t)MTOT * D];
__device__ __nv_bfloat16 g_chh[(size_t)MTOT * D];
__device__ __nv_bfloat16 g_cll[(size_t)MTOT * D];
__device__ __nv_bfloat16 g_wh[4][(size_t)D * D];   // transposed [n][k]: 0=q 1=k 2=v 3=o
__device__ __nv_bfloat16 g_wl[4][(size_t)D * D];

__device__ __half g_qh[(size_t)MTOT * D];                       // Q fp16, scale folded
__device__ __half g_kh[(size_t)MTOT * D];                       // K fp16
__device__ __half g_vt[(size_t)BATCH * NHEAD * HDIM * SEQ];     // V^T fp16 [b][h][hd][tok]

// ---------------- small helpers --------------------------------------------
__device__ __forceinline__ uint32_t smem_u32(const void* p) {
    return (uint32_t)__cvta_generic_to_shared(p);
}
__device__ __forceinline__ uint32_t lds32(uint32_t addr) {
    uint32_t v;
    asm volatile("ld.shared.b32 %0, [%1];" : "=r"(v) : "r"(addr));
    return v;
}
__device__ __forceinline__ void cp16(uint32_t dst, const void* src) {
    asm volatile("cp.async.cg.shared.global [%0], [%1], 16;" :: "r"(dst), "l"(src) : "memory");
}
#define CP_COMMIT() asm volatile("cp.async.commit_group;" ::: "memory")
#define CP_WAIT0()  asm volatile("cp.async.wait_group 0;" ::: "memory")
#define CP_WAIT1()  asm volatile("cp.async.wait_group 1;" ::: "memory")

__device__ __forceinline__ void mma_bf16(float* c, uint32_t a0, uint32_t a1, uint32_t a2,
                                         uint32_t a3, uint32_t b0, uint32_t b1) {
    asm volatile(
        "mma.sync.aligned.m16n8k16.row.col.f32.bf16.bf16.f32 "
        "{%0,%1,%2,%3}, {%4,%5,%6,%7}, {%8,%9}, {%0,%1,%2,%3};"
        : "+f"(c[0]), "+f"(c[1]), "+f"(c[2]), "+f"(c[3])
        : "r"(a0), "r"(a1), "r"(a2), "r"(a3), "r"(b0), "r"(b1));
}
__device__ __forceinline__ void mma_f16(float* c, uint32_t a0, uint32_t a1, uint32_t a2,
                                        uint32_t a3, uint32_t b0, uint32_t b1) {
    asm volatile(
        "mma.sync.aligned.m16n8k16.row.col.f32.f16.f16.f32 "
        "{%0,%1,%2,%3}, {%4,%5,%6,%7}, {%8,%9}, {%0,%1,%2,%3};"
        : "+f"(c[0]), "+f"(c[1]), "+f"(c[2]), "+f"(c[3])
        : "r"(a0), "r"(a1), "r"(a2), "r"(a3), "r"(b0), "r"(b1));
}
__device__ __forceinline__ uint32_t pack_h2(float a, float b) {
    __half2 h = __floats2half2_rn(a, b);
    return *reinterpret_cast<uint32_t*>(&h);
}

// ---------------- fp32 -> bf16 hi/lo split ---------------------------------
__device__ __forceinline__ void split2(float v, __nv_bfloat16& h, __nv_bfloat16& l) {
    h = __float2bfloat16(v);
    l = __float2bfloat16(v - __bfloat162float(h));
}

__global__ void __launch_bounds__(256) conv_split(const float* __restrict__ src,
                                                  __nv_bfloat16* __restrict__ hi,
                                                  __nv_bfloat16* __restrict__ lo)
{
    int i = blockIdx.x * 256 + threadIdx.x;     // one float4 per thread
    float4 v = ((const float4*)src)[i];
    __nv_bfloat16 h0, h1, h2, h3, l0, l1, l2, l3;
    split2(v.x, h0, l0); split2(v.y, h1, l1);
    split2(v.z, h2, l2); split2(v.w, h3, l3);
    __nv_bfloat162 ph0; ph0.x = h0; ph0.y = h1;
    __nv_bfloat162 ph1; ph1.x = h2; ph1.y = h3;
    __nv_bfloat162 pl0; pl0.x = l0; pl0.y = l1;
    __nv_bfloat162 pl1; pl1.x = l2; pl1.y = l3;
    ((__nv_bfloat162*)hi)[2 * i]     = ph0;
    ((__nv_bfloat162*)hi)[2 * i + 1] = ph1;
    ((__nv_bfloat162*)lo)[2 * i]     = pl0;
    ((__nv_bfloat162*)lo)[2 * i + 1] = pl1;
}

// transpose W[k][n] -> Wt[n][k], split into bf16 hi/lo. block (32,8), grid (32,32,4)
__global__ void __launch_bounds__(256) conv_w(const float* __restrict__ Wq,
                                              const float* __restrict__ Wk,
                                              const float* __restrict__ Wv,
                                              const float* __restrict__ Wo)
{
    const float* W = (blockIdx.z == 0) ? Wq : (blockIdx.z == 1) ? Wk
                   : (blockIdx.z == 2) ? Wv : Wo;
    __nv_bfloat16* th = g_wh[blockIdx.z];
    __nv_bfloat16* tl = g_wl[blockIdx.z];

    __shared__ float t[32][33];
    int n0 = blockIdx.x * 32, k0 = blockIdx.y * 32;
    int tx = threadIdx.x, ty = threadIdx.y;
#pragma unroll
    for (int i = 0; i < 4; i++)
        t[ty + i * 8][tx] = W[(size_t)(k0 + ty + i * 8) * D + n0 + tx];
    __syncthreads();
#pragma unroll
    for (int i = 0; i < 4; i++) {
        float v = t[tx][ty + i * 8];
        __nv_bfloat16 h, l; split2(v, h, l);
        size_t off = (size_t)(n0 + ty + i * 8) * D + k0 + tx;
        th[off] = h; tl[off] = l;
    }
}

// ---------------- mma.sync bf16x3 GEMM --------------------------------------
// C[128x128 tile] = A @ Wt^T, A=[m][k] bf16 hi/lo, Wt=[n][k] bf16 hi/lo.
// BK=32, 2-stage cp.async pipeline. 8 warps: wm=wid&3 (32 rows), wn=wid>>2 (64 cols).
#define GPITCH_B 80                      // bytes per smem row (40 bf16, conflict-free)
#define GTILE_B  (128 * GPITCH_B)        // 10240
#define GSTAGE_B (4 * GTILE_B)           // 40960 (Ah, Al, Bh, Bl)
#define GSMEM    (2 * GSTAGE_B)          // 81920

#define QSCALE (0.125f * 1.4426950408889634f)

template<int MODE>   // 0 = QKV (blockIdx.z picks), 1 = out-proj
__global__ void __launch_bounds__(256, 2) gemm_mma(float* __restrict__ outp,
                                                   const float* __restrict__ bias)
{
    extern __shared__ char sm[];
    const uint32_t smb = smem_u32(sm);
    const int tid = threadIdx.x;
    const int wid = tid >> 5, lane = tid & 31;
    const int g = lane >> 2, tg = lane & 3;
    const int wm = wid & 3, wn = wid >> 2;
    const int n0 = blockIdx.x * 128, m0 = blockIdx.y * 128;
    const int z = (MODE == 0) ? blockIdx.z : 3;

    const __nv_bfloat16* srcb[4] = {
        ((MODE == 0) ? g_xh : g_chh) + (size_t)m0 * D,
        ((MODE == 0) ? g_xl : g_cll) + (size_t)m0 * D,
        g_wh[z] + (size_t)n0 * D,
        g_wl[z] + (size_t)n0 * D };

    // per-stage load: 2048 16B chunks (4 tiles x 128 rows x 4 chunks)
    auto load_stage = [&](int kb, int st) {
#pragma unroll
        for (int i = 0; i < 8; i++) {
            int idx = tid + i * 256;
            int t   = idx >> 9;
            int rid = (idx >> 2) & 127;
            int c   = idx & 3;
            cp16(smb + st * GSTAGE_B + t * GTILE_B + rid * GPITCH_B + c * 16,
                 srcb[t] + (size_t)rid * D + kb * 32 + c * 8);
        }
    };

    float acc[2][8][4];
#pragma unroll
    for (int i = 0; i < 2; i++)
#pragma unroll
        for (int j = 0; j < 8; j++)
#pragma unroll
            for (int c = 0; c < 4; c++) acc[i][j][c] = 0.f;

    load_stage(0, 0); CP_COMMIT();

    for (int kb = 0; kb < 32; kb++) {
        const int st = kb & 1;
        if (kb + 1 < 32) { load_stage(kb + 1, st ^ 1); CP_COMMIT(); CP_WAIT1(); }
        else             { CP_WAIT0(); }
        __syncthreads();

        const uint32_t sb = smb + st * GSTAGE_B;
#pragma unroll
        for (int ks = 0; ks < 2; ks++) {
            const uint32_t cs = (ks * 16 + tg * 2) * 2;
            uint32_t aH[2][4], aL[2][4];
#pragma unroll
            for (int i = 0; i < 2; i++) {
                uint32_t ro = (uint32_t)(wm * 32 + i * 16 + g) * GPITCH_B;
                aH[i][0] = lds32(sb + ro + cs);
                aH[i][1] = lds32(sb + ro + 8 * GPITCH_B + cs);
                aH[i][2] = lds32(sb + ro + cs + 16);
                aH[i][3] = lds32(sb + ro + 8 * GPITCH_B + cs + 16);
                aL[i][0] = lds32(sb + GTILE_B + ro + cs);
                aL[i][1] = lds32(sb + GTILE_B + ro + 8 * GPITCH_B + cs);
                aL[i][2] = lds32(sb + GTILE_B + ro + cs + 16);
                aL[i][3] = lds32(sb + GTILE_B + ro + 8 * GPITCH_B + cs + 16);
            }
#pragma unroll
            for (int j = 0; j < 8; j++) {
                uint32_t bo = (uint32_t)(wn * 64 + j * 8 + g) * GPITCH_B + cs;
                uint32_t bh0 = lds32(sb + 2 * GTILE_B + bo);
                uint32_t bh1 = lds32(sb + 2 * GTILE_B + bo + 16);
                uint32_t bl0 = lds32(sb + 3 * GTILE_B + bo);
                uint32_t bl1 = lds32(sb + 3 * GTILE_B + bo + 16);
#pragma unroll
                for (int i = 0; i < 2; i++) {
                    mma_bf16(acc[i][j], aH[i][0], aH[i][1], aH[i][2], aH[i][3], bh0, bh1);
                    mma_bf16(acc[i][j], aH[i][0], aH[i][1], aH[i][2], aH[i][3], bl0, bl1);
                    mma_bf16(acc[i][j], aL[i][0], aL[i][1], aL[i][2], aL[i][3], bh0, bh1);
                }
            }
        }
        __syncthreads();
    }

    // epilogue
#pragma unroll
    for (int i = 0; i < 2; i++) {
#pragma unroll
        for (int j = 0; j < 8; j++) {
            int row = m0 + wm * 32 + i * 16 + g;
            int col = n0 + wn * 64 + j * 8 + tg * 2;
            float v0 = acc[i][j][0], v1 = acc[i][j][1];
            float v2 = acc[i][j][2], v3 = acc[i][j][3];
            if (MODE == 0) {
                if (z == 0) {       // Q: fold softmax scale + log2(e)
                    v0 *= QSCALE; v1 *= QSCALE; v2 *= QSCALE; v3 *= QSCALE;
                    *(uint32_t*)&g_qh[(size_t)row * D + col]       = pack_h2(v0, v1);
                    *(uint32_t*)&g_qh[(size_t)(row + 8) * D + col] = pack_h2(v2, v3);
                } else if (z == 1) {
                    *(uint32_t*)&g_kh[(size_t)row * D + col]       = pack_h2(v0, v1);
                    *(uint32_t*)&g_kh[(size_t)(row + 8) * D + col] = pack_h2(v2, v3);
                } else {            // V: transpose scatter -> [b][h][hd][tok]
                    int b   = row >> 11;
                    int tok = row & 2047;
                    int h   = col >> 6;
                    int hd  = col & 63;
                    size_t base = ((size_t)(b * NHEAD + h) * HDIM + hd) * SEQ;
                    g_vt[base + tok]            = __float2half(v0);
                    g_vt[base + SEQ + tok]      = __float2half(v1);
                    g_vt[base + tok + 8 * 0 + 0] = g_vt[base + tok]; // no-op keep
                    int tok2 = (row + 8) & 2047;
                    g_vt[base + tok2]           = __float2half(v2);
                    g_vt[base + SEQ + tok2]     = __float2half(v3);
                }
            } else {
                float b0 = bias[col], b1 = bias[col + 1];
                float2 w0 = make_float2(v0 + b0, v1 + b1);
                float2 w1 = make_float2(v2 + b0, v3 + b1);
                *(float2*)&outp[(size_t)row * D + col]       = w0;
                *(float2*)&outp[(size_t)(row + 8) * D + col] = w1;
            }
        }
    }
}

// ---------------- FlashAttention-2 with mma.sync fp16 ----------------------
// CTA: 128 queries x one head. 8 warps, each warp 16 query rows x 64 keys.
// smem: Q[128][72]h + 2 stages of (K[64][72]h + Vt[64][72]h). pitch 144B.
#define APITCH  144
#define AQ_B    (128 * APITCH)          // 18432
#define AKV_B   (64 * APITCH)           // 9216
#define ASTAGE  (2 * AKV_B)             // 18432
#define ASMEM   (AQ_B + 2 * ASTAGE)     // 55296

__global__ void __launch_bounds__(256, 2) attn_mma()
{
    extern __shared__ char sm[];
    const uint32_t smb = smem_u32(sm);
    const int tid = threadIdx.x, wid = tid >> 5, lane = tid & 31;
    const int g = lane >> 2, tg = lane & 3;
    const int mb = blockIdx.x, h = blockIdx.y, b = blockIdx.z;
    const int m0 = mb * 128, bS = b * SEQ;
    const int nt = 2 * mb + 2;

    const __half* Qg = g_qh + (size_t)(bS + m0) * D + h * 64;
    const __half* Kg = g_kh + (size_t)bS * D + h * 64;
    const __half* Vg = g_vt + (size_t)(b * NHEAD + h) * HDIM * SEQ;

    auto load_tile = [&](int kt, int st) {
        int n0 = kt * 64;
#pragma unroll
        for (int i = 0; i < 2; i++) {
            int idx = tid + i * 256;
            int rid = idx >> 3, c = idx & 7;
            cp16(smb + AQ_B + st * ASTAGE + rid * APITCH + c * 16,
                 Kg + (size_t)(n0 + rid) * D + c * 8);
            cp16(smb + AQ_B + st * ASTAGE + AKV_B + rid * APITCH + c * 16,
                 Vg + (size_t)rid * SEQ + n0 + c * 8);
        }
    };

    // prologue: Q + tile0 (group0), tile1 (group1)
#pragma unroll
    for (int i = 0; i < 4; i++) {
        int idx = tid + i * 256;
        int rid = idx >> 3, c = idx & 7;
        cp16(smb + rid * APITCH + c * 16, Qg + (size_t)rid * D + c * 8);
    }
    load_tile(0, 0); CP_COMMIT();
    load_tile(1, 1); CP_COMMIT(); CP_WAIT1();    // nt >= 2 always
    __syncthreads();

    // Q fragments (reused across all key tiles)
    uint32_t qf[4][4];
    {
        uint32_t ro = (uint32_t)(wid * 16 + g) * APITCH;
#pragma unroll
        for (int ks = 0; ks < 4; ks++) {
            uint32_t cs = (ks * 16 + tg * 2) * 2;
            qf[ks][0] = lds32(smb + ro + cs);
            qf[ks][1] = lds32(smb + ro + 8 * APITCH + cs);
            qf[ks][2] = lds32(smb + ro + cs + 16);
            qf[ks][3] = lds32(smb + ro + 8 * APITCH + cs + 16);
        }
    }

    float oacc[8][4];
#pragma unroll
    for (int j = 0; j < 8; j++)
#pragma unroll
        for (int c = 0; c < 4; c++) oacc[j][c] = 0.f;
    float mp0 = -1e30f, mp1 = -1e30f, lsum0 = 0.f, lsum1 = 0.f;

    const int r0 = m0 + wid * 16 + g;
    const int r1 = r0 + 8;

    for (int kt = 0; kt < nt; kt++) {
        const int st = kt & 1;
        const uint32_t kb = smb + AQ_B + st * ASTAGE;
        const uint32_t vb = kb + AKV_B;

        // S = Q @ K^T  (per warp: 16 x 64)
        float s[8][4];
#pragma unroll
        for (int j = 0; j < 8; j++) {
#pragma unroll
            for (int c = 0; c < 4; c++) s[j][c] = 0.f;
            uint32_t bo = (uint32_t)(j * 8 + g) * APITCH;
#pragma unroll
            for (int ks = 0; ks < 4; ks++) {
                uint32_t cs = (ks * 16 + tg * 2) * 2;
                uint32_t b0 = lds32(kb + bo + cs);
                uint32_t b1 = lds32(kb + bo + cs + 16);
                mma_f16(s[j], qf[ks][0], qf[ks][1], qf[ks][2], qf[ks][3], b0, b1);
            }
        }

        // causal mask (only near-diagonal tiles need it)
        const int n0k = kt * 64;
        if (n0k + 63 > r0) {
#pragma unroll
            for (int j = 0; j < 8; j++) {
                int c0 = n0k + j * 8 + tg * 2;
                if (c0 > r0)     s[j][0] = -1e30f;
                if (c0 + 1 > r0) s[j][1] = -1e30f;
                if (c0 > r1)     s[j][2] = -1e30f;
                if (c0 + 1 > r1) s[j][3] = -1e30f;
            }
        }

        // online softmax (rows g / g+8; quad lanes share a row)
        float mx0 = -1e30f, mx1 = -1e30f;
#pragma unroll
        for (int j = 0; j < 8; j++) {
            mx0 = fmaxf(mx0, fmaxf(s[j][0], s[j][1]));
            mx1 = fmaxf(mx1, fmaxf(s[j][2], s[j][3]));
        }
        mx0 = fmaxf(mx0, __shfl_xor_sync(0xffffffffu, mx0, 1));
        mx0 = fmaxf(mx0, __shfl_xor_sync(0xffffffffu, mx0, 2));
        mx1 = fmaxf(mx1, __shfl_xor_sync(0xffffffffu, mx1, 1));
        mx1 = fmaxf(mx1, __shfl_xor_sync(0xffffffffu, mx1, 2));
        float mn0 = fmaxf(mp0, mx0), mn1 = fmaxf(mp1, mx1);
        float al0 = exp2f(mp0 - mn0), al1 = exp2f(mp1 - mn1);
        mp0 = mn0; mp1 = mn1;
        float sum0 = 0.f, sum1 = 0.f;
#pragma unroll
        for (int j = 0; j < 8; j++) {
            s[j][0] = exp2f(s[j][0] - mn0);
            s[j][1] = exp2f(s[j][1] - mn0);
            s[j][2] = exp2f(s[j][2] - mn1);
            s[j][3] = exp2f(s[j][3] - mn1);
            sum0 += s[j][0] + s[j][1];
            sum1 += s[j][2] + s[j][3];
        }
        lsum0 = lsum0 * al0 + sum0;
        lsum1 = lsum1 * al1 + sum1;
#pragma unroll
        for (int j = 0; j < 8; j++) {
            oacc[j][0] *= al0; oacc[j][1] *= al0;
            oacc[j][2] *= al1; oacc[j][3] *= al1;
        }

        // O += P @ V   (P stays in registers: S-frag == A-frag layout)
#pragma unroll
        for (int ks = 0; ks < 4; ks++) {
            uint32_t a0 = pack_h2(s[2 * ks][0],     s[2 * ks][1]);
            uint32_t a1 = pack_h2(s[2 * ks][2],     s[2 * ks][3]);
            uint32_t a2 = pack_h2(s[2 * ks + 1][0], s[2 * ks + 1][1]);
            uint32_t a3 = pack_h2(s[2 * ks + 1][2], s[2 * ks + 1][3]);
            uint32_t cs = (ks * 16 + tg * 2) * 2;
#pragma unroll
            for (int jn = 0; jn < 8; jn++) {
                uint32_t bo = (uint32_t)(jn * 8 + g) * APITCH + cs;
                uint32_t b0 = lds32(vb + bo);
                uint32_t b1 = lds32(vb + bo + 16);
                mma_f16(oacc[jn], a0, a1, a2, a3, b0, b1);
            }
        }

        if (kt + 1 >= nt) break;
        __syncthreads();                 // done reading buffer st
        if (kt + 2 < nt) { load_tile(kt + 2, st); CP_COMMIT(); CP_WAIT1(); }
        else             { CP_WAIT0(); }
        __syncthreads();
    }

    // finalize: full row sums across the quad, normalize, write ctx fp32
    lsum0 += __shfl_xor_sync(0xffffffffu, lsum0, 1);
    lsum0 += __shfl_xor_sync(0xffffffffu, lsum0, 2);
    lsum1 += __shfl_xor_sync(0xffffffffu, lsum1, 1);
    lsum1 += __shfl_xor_sync(0xffffffffu, lsum1, 2);
    float inv0 = 1.f / lsum0, inv1 = 1.f / lsum1;

    float* base0 = g_ctx + (size_t)(bS + m0 + wid * 16 + g) * D + h * 64;
#pragma unroll
    for (int jn = 0; jn < 8; jn++) {
        int off = jn * 8 + tg * 2;
        *(float2*)(base0 + off) = make_float2(oacc[jn][0] * inv0, oacc[jn][1] * inv0);
        *(float2*)(base0 + (size_t)8 * D + off) =
            make_float2(oacc[jn][2] * inv1, oacc[jn][3] * inv1);
    }
}

// ---------------------------------------------------------------------------
extern "C" void kernel_launch(void* const* d_in, const int* in_sizes, int n_in,
                              void* d_out, int out_size)
{
    const float* x  = (const float*)d_in[0];
    const float* Wq = (const float*)d_in[1];
    const float* Wk = (const float*)d_in[2];
    const float* Wv = (const float*)d_in[3];
    const float* Wo = (const float*)d_in[4];
    const float* bo = (const float*)d_in[5];
    float* out = (float*)d_out;

    static bool attr_set = false;
    if (!attr_set) {
        cudaFuncSetAttribute(gemm_mma<0>, cudaFuncAttributeMaxDynamicSharedMemorySize, GSMEM);
        cudaFuncSetAttribute(gemm_mma<1>, cudaFuncAttributeMaxDynamicSharedMemorySize, GSMEM);
        cudaFuncSetAttribute(attn_mma,    cudaFuncAttributeMaxDynamicSharedMemorySize, ASMEM);
        attr_set = true;
    }

    float* ctx;
    __nv_bfloat16 *xh, *xl, *ch, *cl;
    cudaGetSymbolAddress((void**)&ctx, g_ctx);
    cudaGetSymbolAddress((void**)&xh,  g_xh);
    cudaGetSymbolAddress((void**)&xl,  g_xl);
    cudaGetSymbolAddress((void**)&ch,  g_chh);
    cudaGetSymbolAddress((void**)&cl,  g_cll);

    conv_split<<<(MTOT * D / 4) / 256, 256>>>(x, xh, xl);
    conv_w<<<dim3(32, 32, 4), dim3(32, 8)>>>(Wq, Wk, Wv, Wo);
    gemm_mma<0><<<dim3(8, 64, 3), 256, GSMEM>>>(nullptr, nullptr);
    attn_mma<<<dim3(SEQ / 128, NHEAD, BATCH), 256, ASMEM>>>();
    conv_split<<<(MTOT * D / 4) / 256, 256>>>(ctx, ch, cl);
    gemm_mma<1><<<dim3(8, 64, 1), 256, GSMEM>>>(out, bo);
}

// round 4
// speedup vs baseline: 3.6800x; 1.0909x over previous
#include <cuda_runtime.h>
#include <cuda_bf16.h>
#include <cuda_fp16.h>
#include <cstdint>

#define D      1024
#define NHEAD  16
#define HDIM   64
#define BATCH  4
#define SEQ    2048
#define MTOT   (BATCH*SEQ)   // 8192

// ---------------- scratch (__device__ globals; no allocation allowed) ------
__device__ float g_ctx[(size_t)MTOT * D];

__device__ __nv_bfloat16 g_xh[(size_t)MTOT * D];
__device__ __nv_bfloat16 g_xl[(size_t)MTOT * D];
__device__ __nv_bfloat16 g_chh[(size_t)MTOT * D];
__device__ __nv_bfloat16 g_cll[(size_t)MTOT * D];
__device__ __nv_bfloat16 g_wh[4][(size_t)D * D];   // transposed [n][k]: 0=q 1=k 2=v 3=o
__device__ __nv_bfloat16 g_wl[4][(size_t)D * D];

__device__ __half g_qh[(size_t)MTOT * D];          // Q fp16, scale folded
__device__ __half g_kh[(size_t)MTOT * D];          // K fp16
__device__ __half g_vh[(size_t)MTOT * D];          // V fp16 (row-major [tok][hd])

// ---------------- small helpers --------------------------------------------
__device__ __forceinline__ uint32_t smem_u32(const void* p) {
    return (uint32_t)__cvta_generic_to_shared(p);
}
__device__ __forceinline__ void cp16(uint32_t dst, const void* src) {
    asm volatile("cp.async.cg.shared.global [%0], [%1], 16;" :: "r"(dst), "l"(src) : "memory");
}
#define CP_COMMIT() asm volatile("cp.async.commit_group;" ::: "memory")
#define CP_WAIT0()  asm volatile("cp.async.wait_group 0;" ::: "memory")
#define CP_WAIT1()  asm volatile("cp.async.wait_group 1;" ::: "memory")

__device__ __forceinline__ void ldsm4(uint32_t* r, uint32_t a) {
    asm volatile("ldmatrix.sync.aligned.m8n8.x4.shared.b16 {%0,%1,%2,%3}, [%4];"
        : "=r"(r[0]), "=r"(r[1]), "=r"(r[2]), "=r"(r[3]) : "r"(a));
}
__device__ __forceinline__ void ldsm4t(uint32_t* r, uint32_t a) {
    asm volatile("ldmatrix.sync.aligned.m8n8.x4.trans.shared.b16 {%0,%1,%2,%3}, [%4];"
        : "=r"(r[0]), "=r"(r[1]), "=r"(r[2]), "=r"(r[3]) : "r"(a));
}

__device__ __forceinline__ void mma_bf16(float* c, const uint32_t* a, uint32_t b0, uint32_t b1) {
    asm volatile(
        "mma.sync.aligned.m16n8k16.row.col.f32.bf16.bf16.f32 "
        "{%0,%1,%2,%3}, {%4,%5,%6,%7}, {%8,%9}, {%0,%1,%2,%3};"
        : "+f"(c[0]), "+f"(c[1]), "+f"(c[2]), "+f"(c[3])
        : "r"(a[0]), "r"(a[1]), "r"(a[2]), "r"(a[3]), "r"(b0), "r"(b1));
}
__device__ __forceinline__ void mma_f16(float* c, uint32_t a0, uint32_t a1, uint32_t a2,
                                        uint32_t a3, uint32_t b0, uint32_t b1) {
    asm volatile(
        "mma.sync.aligned.m16n8k16.row.col.f32.f16.f16.f32 "
        "{%0,%1,%2,%3}, {%4,%5,%6,%7}, {%8,%9}, {%0,%1,%2,%3};"
        : "+f"(c[0]), "+f"(c[1]), "+f"(c[2]), "+f"(c[3])
        : "r"(a0), "r"(a1), "r"(a2), "r"(a3), "r"(b0), "r"(b1));
}
__device__ __forceinline__ uint32_t pack_h2(float a, float b) {
    __half2 h = __floats2half2_rn(a, b);
    return *reinterpret_cast<uint32_t*>(&h);
}

// ---------------- fp32 -> bf16 hi/lo split ---------------------------------
__device__ __forceinline__ void split2(float v, __nv_bfloat16& h, __nv_bfloat16& l) {
    h = __float2bfloat16(v);
    l = __float2bfloat16(v - __bfloat162float(h));
}

__global__ void __launch_bounds__(256) conv_split(const float* __restrict__ src,
                                                  __nv_bfloat16* __restrict__ hi,
                                                  __nv_bfloat16* __restrict__ lo)
{
    int i = blockIdx.x * 256 + threadIdx.x;
    float4 v = ((const float4*)src)[i];
    __nv_bfloat16 h0, h1, h2, h3, l0, l1, l2, l3;
    split2(v.x, h0, l0); split2(v.y, h1, l1);
    split2(v.z, h2, l2); split2(v.w, h3, l3);
    __nv_bfloat162 ph0; ph0.x = h0; ph0.y = h1;
    __nv_bfloat162 ph1; ph1.x = h2; ph1.y = h3;
    __nv_bfloat162 pl0; pl0.x = l0; pl0.y = l1;
    __nv_bfloat162 pl1; pl1.x = l2; pl1.y = l3;
    ((__nv_bfloat162*)hi)[2 * i]     = ph0;
    ((__nv_bfloat162*)hi)[2 * i + 1] = ph1;
    ((__nv_bfloat162*)lo)[2 * i]     = pl0;
    ((__nv_bfloat162*)lo)[2 * i + 1] = pl1;
}

__global__ void __launch_bounds__(256) conv_w(const float* __restrict__ Wq,
                                              const float* __restrict__ Wk,
                                              const float* __restrict__ Wv,
                                              const float* __restrict__ Wo)
{
    const float* W = (blockIdx.z == 0) ? Wq : (blockIdx.z == 1) ? Wk
                   : (blockIdx.z == 2) ? Wv : Wo;
    __nv_bfloat16* th = g_wh[blockIdx.z];
    __nv_bfloat16* tl = g_wl[blockIdx.z];

    __shared__ float t[32][33];
    int n0 = blockIdx.x * 32, k0 = blockIdx.y * 32;
    int tx = threadIdx.x, ty = threadIdx.y;
#pragma unroll
    for (int i = 0; i < 4; i++)
        t[ty + i * 8][tx] = W[(size_t)(k0 + ty + i * 8) * D + n0 + tx];
    __syncthreads();
#pragma unroll
    for (int i = 0; i < 4; i++) {
        float v = t[tx][ty + i * 8];
        __nv_bfloat16 h, l; split2(v, h, l);
        size_t off = (size_t)(n0 + ty + i * 8) * D + k0 + tx;
        th[off] = h; tl[off] = l;
    }
}

// ---------------- mma.sync bf16x3 GEMM --------------------------------------
#define GPITCH_B 80
#define GTILE_B  (128 * GPITCH_B)        // 10240
#define GSTAGE_B (4 * GTILE_B)           // 40960 (Ah, Al, Bh, Bl)
#define GSMEM    (2 * GSTAGE_B)          // 81920

#define QSCALE (0.125f * 1.4426950408889634f)

template<int MODE>   // 0 = QKV (blockIdx.z picks), 1 = out-proj
__global__ void __launch_bounds__(256, 2) gemm_mma(float* __restrict__ outp,
                                                   const float* __restrict__ bias)
{
    extern __shared__ char sm[];
    const uint32_t smb = smem_u32(sm);
    const int tid = threadIdx.x;
    const int wid = tid >> 5, lane = tid & 31;
    const int g = lane >> 2, tg = lane & 3;
    const int wm = wid & 3, wn = wid >> 2;
    const int n0 = blockIdx.x * 128, m0 = blockIdx.y * 128;
    const int z = (MODE == 0) ? blockIdx.z : 3;

    // ldmatrix per-lane offsets (bit3 = row+8, bit4 = k+8 for A; swapped for B)
    const uint32_t aoff = (uint32_t)((lane & 7) + ((lane >> 3) & 1) * 8) * GPITCH_B
                        + ((lane >> 4) & 1) * 16;
    const uint32_t boff = (uint32_t)((lane & 7) + ((lane >> 4) & 1) * 8) * GPITCH_B
                        + ((lane >> 3) & 1) * 16;

    const __nv_bfloat16* srcb[4] = {
        ((MODE == 0) ? g_xh : g_chh) + (size_t)m0 * D,
        ((MODE == 0) ? g_xl : g_cll) + (size_t)m0 * D,
        g_wh[z] + (size_t)n0 * D,
        g_wl[z] + (size_t)n0 * D };

    auto load_stage = [&](int kb, int st) {
#pragma unroll
        for (int i = 0; i < 8; i++) {
            int idx = tid + i * 256;
            int t   = idx >> 9;
            int rid = (idx >> 2) & 127;
            int c   = idx & 3;
            cp16(smb + st * GSTAGE_B + t * GTILE_B + rid * GPITCH_B + c * 16,
                 srcb[t] + (size_t)rid * D + kb * 32 + c * 8);
        }
    };

    float acc[2][8][4];
#pragma unroll
    for (int i = 0; i < 2; i++)
#pragma unroll
        for (int j = 0; j < 8; j++)
#pragma unroll
            for (int c = 0; c < 4; c++) acc[i][j][c] = 0.f;

    load_stage(0, 0); CP_COMMIT();

    for (int kb = 0; kb < 32; kb++) {
        const int st = kb & 1;
        if (kb + 1 < 32) { load_stage(kb + 1, st ^ 1); CP_COMMIT(); CP_WAIT1(); }
        else             { CP_WAIT0(); }
        __syncthreads();

        const uint32_t sb    = smb + st * GSTAGE_B;
        const uint32_t abase = sb + (uint32_t)(wm * 32) * GPITCH_B + aoff;
        const uint32_t bbase = sb + 2 * GTILE_B + (uint32_t)(wn * 64) * GPITCH_B + boff;

#pragma unroll
        for (int ks = 0; ks < 2; ks++) {
            uint32_t aH[2][4], aL[2][4];
#pragma unroll
            for (int i = 0; i < 2; i++) {
                uint32_t ar = abase + (uint32_t)(i * 16) * GPITCH_B + ks * 32;
                ldsm4(aH[i], ar);
                ldsm4(aL[i], ar + GTILE_B);
            }
#pragma unroll
            for (int p = 0; p < 4; p++) {
                uint32_t br = bbase + (uint32_t)(p * 16) * GPITCH_B + ks * 32;
                uint32_t bh[4], bl[4];
                ldsm4(bh, br);
                ldsm4(bl, br + GTILE_B);
#pragma unroll
                for (int i = 0; i < 2; i++) {
                    mma_bf16(acc[i][2 * p],     aH[i], bh[0], bh[1]);
                    mma_bf16(acc[i][2 * p + 1], aH[i], bh[2], bh[3]);
                    mma_bf16(acc[i][2 * p],     aH[i], bl[0], bl[1]);
                    mma_bf16(acc[i][2 * p + 1], aH[i], bl[2], bl[3]);
                    mma_bf16(acc[i][2 * p],     aL[i], bh[0], bh[1]);
                    mma_bf16(acc[i][2 * p + 1], aL[i], bh[2], bh[3]);
                }
            }
        }
        __syncthreads();
    }

    // epilogue
#pragma unroll
    for (int i = 0; i < 2; i++) {
#pragma unroll
        for (int j = 0; j < 8; j++) {
            int row = m0 + wm * 32 + i * 16 + g;
            int col = n0 + wn * 64 + j * 8 + tg * 2;
            float v0 = acc[i][j][0], v1 = acc[i][j][1];
            float v2 = acc[i][j][2], v3 = acc[i][j][3];
            if (MODE == 0) {
                if (z == 0) {       // Q: fold softmax scale + log2(e)
                    v0 *= QSCALE; v1 *= QSCALE; v2 *= QSCALE; v3 *= QSCALE;
                    *(uint32_t*)&g_qh[(size_t)row * D + col]       = pack_h2(v0, v1);
                    *(uint32_t*)&g_qh[(size_t)(row + 8) * D + col] = pack_h2(v2, v3);
                } else if (z == 1) {
                    *(uint32_t*)&g_kh[(size_t)row * D + col]       = pack_h2(v0, v1);
                    *(uint32_t*)&g_kh[(size_t)(row + 8) * D + col] = pack_h2(v2, v3);
                } else {            // V: row-major fp16 (transposed later via ldmatrix.trans)
                    *(uint32_t*)&g_vh[(size_t)row * D + col]       = pack_h2(v0, v1);
                    *(uint32_t*)&g_vh[(size_t)(row + 8) * D + col] = pack_h2(v2, v3);
                }
            } else {
                float b0 = bias[col], b1 = bias[col + 1];
                *(float2*)&outp[(size_t)row * D + col]       = make_float2(v0 + b0, v1 + b1);
                *(float2*)&outp[(size_t)(row + 8) * D + col] = make_float2(v2 + b0, v3 + b1);
            }
        }
    }
}

// ---------------- FlashAttention-2 with mma.sync fp16 ----------------------
// CTA: 128 queries x one head. 8 warps, each warp 16 query rows x 64 keys.
#define APITCH  144
#define AQ_B    (128 * APITCH)          // 18432
#define AKV_B   (64 * APITCH)           // 9216
#define ASTAGE  (2 * AKV_B)             // 18432
#define ASMEM   (AQ_B + 2 * ASTAGE)     // 55296

__global__ void __launch_bounds__(256, 2) attn_mma()
{
    extern __shared__ char sm[];
    const uint32_t smb = smem_u32(sm);
    const int tid = threadIdx.x, wid = tid >> 5, lane = tid & 31;
    const int g = lane >> 2, tg = lane & 3;
    const int mb = blockIdx.x, h = blockIdx.y, b = blockIdx.z;
    const int m0 = mb * 128, bS = b * SEQ;
    const int nt = 2 * mb + 2;

    // ldmatrix lane offsets (APITCH)
    const uint32_t aoff = (uint32_t)((lane & 7) + ((lane >> 3) & 1) * 8) * APITCH
                        + ((lane >> 4) & 1) * 16;   // Q (A-frag) and V (trans B-frag)
    const uint32_t boff = (uint32_t)((lane & 7) + ((lane >> 4) & 1) * 8) * APITCH
                        + ((lane >> 3) & 1) * 16;   // K (B-frag)

    const __half* Qg = g_qh + (size_t)(bS + m0) * D + h * 64;
    const __half* Kg = g_kh + (size_t)bS * D + h * 64;
    const __half* Vg = g_vh + (size_t)bS * D + h * 64;

    auto load_tile = [&](int kt, int st) {
        int n0 = kt * 64;
#pragma unroll
        for (int i = 0; i < 2; i++) {
            int idx = tid + i * 256;
            int rid = idx >> 3, c = idx & 7;
            cp16(smb + AQ_B + st * ASTAGE + rid * APITCH + c * 16,
                 Kg + (size_t)(n0 + rid) * D + c * 8);
            cp16(smb + AQ_B + st * ASTAGE + AKV_B + rid * APITCH + c * 16,
                 Vg + (size_t)(n0 + rid) * D + c * 8);
        }
    };

#pragma unroll
    for (int i = 0; i < 4; i++) {
        int idx = tid + i * 256;
        int rid = idx >> 3, c = idx & 7;
        cp16(smb + rid * APITCH + c * 16, Qg + (size_t)rid * D + c * 8);
    }
    load_tile(0, 0); CP_COMMIT();
    load_tile(1, 1); CP_COMMIT(); CP_WAIT1();
    __syncthreads();

    // Q fragments (reused across all key tiles)
    uint32_t qf[4][4];
    {
        uint32_t qbase = smb + (uint32_t)(wid * 16) * APITCH + aoff;
#pragma unroll
        for (int ks = 0; ks < 4; ks++) ldsm4(qf[ks], qbase + ks * 32);
    }

    float oacc[8][4];
#pragma unroll
    for (int j = 0; j < 8; j++)
#pragma unroll
        for (int c = 0; c < 4; c++) oacc[j][c] = 0.f;
    float mp0 = -1e30f, mp1 = -1e30f, lsum0 = 0.f, lsum1 = 0.f;

    const int r0 = m0 + wid * 16 + g;
    const int r1 = r0 + 8;

    for (int kt = 0; kt < nt; kt++) {
        const int st = kt & 1;
        const uint32_t kb = smb + AQ_B + st * ASTAGE;
        const uint32_t vb = kb + AKV_B;

        // S = Q @ K^T  (per warp: 16 x 64)
        float s[8][4];
#pragma unroll
        for (int j = 0; j < 8; j++)
#pragma unroll
            for (int c = 0; c < 4; c++) s[j][c] = 0.f;

#pragma unroll
        for (int ks = 0; ks < 4; ks++) {
#pragma unroll
            for (int p = 0; p < 4; p++) {
                uint32_t kf[4];
                ldsm4(kf, kb + (uint32_t)(p * 16) * APITCH + ks * 32 + boff);
                mma_f16(s[2 * p],     qf[ks][0], qf[ks][1], qf[ks][2], qf[ks][3], kf[0], kf[1]);
                mma_f16(s[2 * p + 1], qf[ks][0], qf[ks][1], qf[ks][2], qf[ks][3], kf[2], kf[3]);
            }
        }

        // causal mask
        const int n0k = kt * 64;
        if (n0k + 63 > r0) {
#pragma unroll
            for (int j = 0; j < 8; j++) {
                int c0 = n0k + j * 8 + tg * 2;
                if (c0 > r0)     s[j][0] = -1e30f;
                if (c0 + 1 > r0) s[j][1] = -1e30f;
                if (c0 > r1)     s[j][2] = -1e30f;
                if (c0 + 1 > r1) s[j][3] = -1e30f;
            }
        }

        // online softmax
        float mx0 = -1e30f, mx1 = -1e30f;
#pragma unroll
        for (int j = 0; j < 8; j++) {
            mx0 = fmaxf(mx0, fmaxf(s[j][0], s[j][1]));
            mx1 = fmaxf(mx1, fmaxf(s[j][2], s[j][3]));
        }
        mx0 = fmaxf(mx0, __shfl_xor_sync(0xffffffffu, mx0, 1));
        mx0 = fmaxf(mx0, __shfl_xor_sync(0xffffffffu, mx0, 2));
        mx1 = fmaxf(mx1, __shfl_xor_sync(0xffffffffu, mx1, 1));
        mx1 = fmaxf(mx1, __shfl_xor_sync(0xffffffffu, mx1, 2));
        float mn0 = fmaxf(mp0, mx0), mn1 = fmaxf(mp1, mx1);
        float al0 = exp2f(mp0 - mn0), al1 = exp2f(mp1 - mn1);
        mp0 = mn0; mp1 = mn1;
        float sum0 = 0.f, sum1 = 0.f;
#pragma unroll
        for (int j = 0; j < 8; j++) {
            s[j][0] = exp2f(s[j][0] - mn0);
            s[j][1] = exp2f(s[j][1] - mn0);
            s[j][2] = exp2f(s[j][2] - mn1);
            s[j][3] = exp2f(s[j][3] - mn1);
            sum0 += s[j][0] + s[j][1];
            sum1 += s[j][2] + s[j][3];
        }
        lsum0 = lsum0 * al0 + sum0;
        lsum1 = lsum1 * al1 + sum1;
#pragma unroll
        for (int j = 0; j < 8; j++) {
            oacc[j][0] *= al0; oacc[j][1] *= al0;
            oacc[j][2] *= al1; oacc[j][3] *= al1;
        }

        // O += P @ V   (V fragments via ldmatrix.trans from [tok][hd] tile)
#pragma unroll
        for (int ks = 0; ks < 4; ks++) {
            uint32_t a0 = pack_h2(s[2 * ks][0],     s[2 * ks][1]);
            uint32_t a1 = pack_h2(s[2 * ks][2],     s[2 * ks][3]);
            uint32_t a2 = pack_h2(s[2 * ks + 1][0], s[2 * ks + 1][1]);
            uint32_t a3 = pack_h2(s[2 * ks + 1][2], s[2 * ks + 1][3]);
#pragma unroll
            for (int p = 0; p < 4; p++) {
                uint32_t vf[4];
                ldsm4t(vf, vb + (uint32_t)(ks * 16) * APITCH + p * 32 + aoff);
                mma_f16(oacc[2 * p],     a0, a1, a2, a3, vf[0], vf[1]);
                mma_f16(oacc[2 * p + 1], a0, a1, a2, a3, vf[2], vf[3]);
            }
        }

        if (kt + 1 >= nt) break;
        __syncthreads();
        if (kt + 2 < nt) { load_tile(kt + 2, st); CP_COMMIT(); CP_WAIT1(); }
        else             { CP_WAIT0(); }
        __syncthreads();
    }

    // finalize
    lsum0 += __shfl_xor_sync(0xffffffffu, lsum0, 1);
    lsum0 += __shfl_xor_sync(0xffffffffu, lsum0, 2);
    lsum1 += __shfl_xor_sync(0xffffffffu, lsum1, 1);
    lsum1 += __shfl_xor_sync(0xffffffffu, lsum1, 2);
    float inv0 = 1.f / lsum0, inv1 = 1.f / lsum1;

    float* base0 = g_ctx + (size_t)(bS + m0 + wid * 16 + g) * D + h * 64;
#pragma unroll
    for (int jn = 0; jn < 8; jn++) {
        int off = jn * 8 + tg * 2;
        *(float2*)(base0 + off) = make_float2(oacc[jn][0] * inv0, oacc[jn][1] * inv0);
        *(float2*)(base0 + (size_t)8 * D + off) =
            make_float2(oacc[jn][2] * inv1, oacc[jn][3] * inv1);
    }
}

// ---------------------------------------------------------------------------
extern "C" void kernel_launch(void* const* d_in, const int* in_sizes, int n_in,
                              void* d_out, int out_size)
{
    const float* x  = (const float*)d_in[0];
    const float* Wq = (const float*)d_in[1];
    const float* Wk = (const float*)d_in[2];
    const float* Wv = (const float*)d_in[3];
    const float* Wo = (const float*)d_in[4];
    const float* bo = (const float*)d_in[5];
    float* out = (float*)d_out;

    static bool attr_set = false;
    if (!attr_set) {
        cudaFuncSetAttribute(gemm_mma<0>, cudaFuncAttributeMaxDynamicSharedMemorySize, GSMEM);
        cudaFuncSetAttribute(gemm_mma<1>, cudaFuncAttributeMaxDynamicSharedMemorySize, GSMEM);
        cudaFuncSetAttribute(attn_mma,    cudaFuncAttributeMaxDynamicSharedMemorySize, ASMEM);
        attr_set = true;
    }

    float* ctx;
    __nv_bfloat16 *xh, *xl, *ch, *cl;
    cudaGetSymbolAddress((void**)&ctx, g_ctx);
    cudaGetSymbolAddress((void**)&xh,  g_xh);
    cudaGetSymbolAddress((void**)&xl,  g_xl);
    cudaGetSymbolAddress((void**)&ch,  g_chh);
    cudaGetSymbolAddress((void**)&cl,  g_cll);

    conv_split<<<(MTOT * D / 4) / 256, 256>>>(x, xh, xl);
    conv_w<<<dim3(32, 32, 4), dim3(32, 8)>>>(Wq, Wk, Wv, Wo);
    gemm_mma<0><<<dim3(8, 64, 3), 256, GSMEM>>>(nullptr, nullptr);
    attn_mma<<<dim3(SEQ / 128, NHEAD, BATCH), 256, ASMEM>>>();
    conv_split<<<(MTOT * D / 4) / 256, 256>>>(ctx, ch, cl);
    gemm_mma<1><<<dim3(8, 64, 1), 256, GSMEM>>>(out, bo);
}

// round 5
// speedup vs baseline: 4.7549x; 1.2921x over previous
#include <cuda_runtime.h>
#include <cuda_fp16.h>
#include <cstdint>

#define D      1024
#define NHEAD  16
#define HDIM   64
#define BATCH  4
#define SEQ    2048
#define MTOT   (BATCH*SEQ)   // 8192

// ---------------- scratch (__device__ globals; no allocation allowed) ------
__device__ __half g_xf[(size_t)MTOT * D];          // x as fp16
__device__ __half g_cth[(size_t)MTOT * D];         // ctx as fp16 (attn output)
__device__ __half g_wh[4][(size_t)D * D];          // W^T hi fp16 [n][k]: 0=q 1=k 2=v 3=o
__device__ __half g_wl[4][(size_t)D * D];          // W^T lo fp16

__device__ __half g_qh[(size_t)MTOT * D];          // Q fp16, scale folded
__device__ __half g_kh[(size_t)MTOT * D];          // K fp16
__device__ __half g_vh[(size_t)MTOT * D];          // V fp16 (row-major [tok][hd])

// ---------------- small helpers --------------------------------------------
__device__ __forceinline__ uint32_t smem_u32(const void* p) {
    return (uint32_t)__cvta_generic_to_shared(p);
}
__device__ __forceinline__ void cp16(uint32_t dst, const void* src) {
    asm volatile("cp.async.cg.shared.global [%0], [%1], 16;" :: "r"(dst), "l"(src) : "memory");
}
#define CP_COMMIT() asm volatile("cp.async.commit_group;" ::: "memory")
#define CP_WAIT0()  asm volatile("cp.async.wait_group 0;" ::: "memory")
#define CP_WAIT1()  asm volatile("cp.async.wait_group 1;" ::: "memory")

__device__ __forceinline__ void ldsm4(uint32_t* r, uint32_t a) {
    asm volatile("ldmatrix.sync.aligned.m8n8.x4.shared.b16 {%0,%1,%2,%3}, [%4];"
        : "=r"(r[0]), "=r"(r[1]), "=r"(r[2]), "=r"(r[3]) : "r"(a));
}
__device__ __forceinline__ void ldsm4t(uint32_t* r, uint32_t a) {
    asm volatile("ldmatrix.sync.aligned.m8n8.x4.trans.shared.b16 {%0,%1,%2,%3}, [%4];"
        : "=r"(r[0]), "=r"(r[1]), "=r"(r[2]), "=r"(r[3]) : "r"(a));
}
__device__ __forceinline__ void mma_f16(float* c, uint32_t a0, uint32_t a1, uint32_t a2,
                                        uint32_t a3, uint32_t b0, uint32_t b1) {
    asm volatile(
        "mma.sync.aligned.m16n8k16.row.col.f32.f16.f16.f32 "
        "{%0,%1,%2,%3}, {%4,%5,%6,%7}, {%8,%9}, {%0,%1,%2,%3};"
        : "+f"(c[0]), "+f"(c[1]), "+f"(c[2]), "+f"(c[3])
        : "r"(a0), "r"(a1), "r"(a2), "r"(a3), "r"(b0), "r"(b1));
}
__device__ __forceinline__ uint32_t pack_h2(float a, float b) {
    __half2 h = __floats2half2_rn(a, b);
    return *reinterpret_cast<uint32_t*>(&h);
}

// ---------------- conversions ----------------------------------------------
__global__ void __launch_bounds__(256) conv_x(const float* __restrict__ src,
                                              __half* __restrict__ dst)
{
    int i = blockIdx.x * 256 + threadIdx.x;
    float4 v = ((const float4*)src)[i];
    uint2 o;
    o.x = pack_h2(v.x, v.y);
    o.y = pack_h2(v.z, v.w);
    ((uint2*)dst)[i] = o;
}

// transpose W[k][n] -> Wt[n][k], split into fp16 hi/lo. block (32,8), grid (32,32,4)
__global__ void __launch_bounds__(256) conv_w(const float* __restrict__ Wq,
                                              const float* __restrict__ Wk,
                                              const float* __restrict__ Wv,
                                              const float* __restrict__ Wo)
{
    const float* W = (blockIdx.z == 0) ? Wq : (blockIdx.z == 1) ? Wk
                   : (blockIdx.z == 2) ? Wv : Wo;
    __half* th = g_wh[blockIdx.z];
    __half* tl = g_wl[blockIdx.z];

    __shared__ float t[32][33];
    int n0 = blockIdx.x * 32, k0 = blockIdx.y * 32;
    int tx = threadIdx.x, ty = threadIdx.y;
#pragma unroll
    for (int i = 0; i < 4; i++)
        t[ty + i * 8][tx] = W[(size_t)(k0 + ty + i * 8) * D + n0 + tx];
    __syncthreads();
#pragma unroll
    for (int i = 0; i < 4; i++) {
        float v = t[tx][ty + i * 8];
        __half h = __float2half(v);
        __half l = __float2half(v - __half2float(h));
        size_t off = (size_t)(n0 + ty + i * 8) * D + k0 + tx;
        th[off] = h; tl[off] = l;
    }
}

// ---------------- mma.sync fp16x2 GEMM --------------------------------------
// C = A @ Wt^T, A fp16 [m][k], Wt split hi/lo fp16 [n][k]. 2 MMA passes.
#define GPITCH_B 80
#define GTILE_B  (128 * GPITCH_B)        // 10240
#define GSTAGE_B (3 * GTILE_B)           // 30720 (A, Bh, Bl)
#define GSMEM    (2 * GSTAGE_B)          // 61440

#define QSCALE (0.125f * 1.4426950408889634f)

template<int MODE>   // 0 = QKV (blockIdx.z picks), 1 = out-proj
__global__ void __launch_bounds__(256, 2) gemm_mma(float* __restrict__ outp,
                                                   const float* __restrict__ bias)
{
    extern __shared__ char sm[];
    const uint32_t smb = smem_u32(sm);
    const int tid = threadIdx.x;
    const int wid = tid >> 5, lane = tid & 31;
    const int g = lane >> 2, tg = lane & 3;
    const int wm = wid & 3, wn = wid >> 2;
    const int n0 = blockIdx.x * 128, m0 = blockIdx.y * 128;
    const int z = (MODE == 0) ? blockIdx.z : 3;

    const uint32_t aoff = (uint32_t)((lane & 7) + ((lane >> 3) & 1) * 8) * GPITCH_B
                        + ((lane >> 4) & 1) * 16;
    const uint32_t boff = (uint32_t)((lane & 7) + ((lane >> 4) & 1) * 8) * GPITCH_B
                        + ((lane >> 3) & 1) * 16;

    const __half* srcb[3] = {
        ((MODE == 0) ? g_xf : g_cth) + (size_t)m0 * D,
        g_wh[z] + (size_t)n0 * D,
        g_wl[z] + (size_t)n0 * D };

    // per stage: 3 tiles x 128 rows x 4 chunks = 1536 chunks, 6 per thread
    auto load_stage = [&](int kb, int st) {
#pragma unroll
        for (int i = 0; i < 6; i++) {
            int idx = tid + i * 256;
            int t   = idx >> 9;
            int rid = (idx >> 2) & 127;
            int c   = idx & 3;
            cp16(smb + st * GSTAGE_B + t * GTILE_B + rid * GPITCH_B + c * 16,
                 srcb[t] + (size_t)rid * D + kb * 32 + c * 8);
        }
    };

    float acc[2][8][4];
#pragma unroll
    for (int i = 0; i < 2; i++)
#pragma unroll
        for (int j = 0; j < 8; j++)
#pragma unroll
            for (int c = 0; c < 4; c++) acc[i][j][c] = 0.f;

    load_stage(0, 0); CP_COMMIT();

    for (int kb = 0; kb < 32; kb++) {
        const int st = kb & 1;
        if (kb + 1 < 32) { load_stage(kb + 1, st ^ 1); CP_COMMIT(); CP_WAIT1(); }
        else             { CP_WAIT0(); }
        __syncthreads();

        const uint32_t sb    = smb + st * GSTAGE_B;
        const uint32_t abase = sb + (uint32_t)(wm * 32) * GPITCH_B + aoff;
        const uint32_t bbase = sb + GTILE_B + (uint32_t)(wn * 64) * GPITCH_B + boff;

#pragma unroll
        for (int ks = 0; ks < 2; ks++) {
            uint32_t aF[2][4];
#pragma unroll
            for (int i = 0; i < 2; i++)
                ldsm4(aF[i], abase + (uint32_t)(i * 16) * GPITCH_B + ks * 32);
#pragma unroll
            for (int p = 0; p < 4; p++) {
                uint32_t br = bbase + (uint32_t)(p * 16) * GPITCH_B + ks * 32;
                uint32_t bh[4], bl[4];
                ldsm4(bh, br);
                ldsm4(bl, br + GTILE_B);
#pragma unroll
                for (int i = 0; i < 2; i++) {
                    mma_f16(acc[i][2 * p],     aF[i][0], aF[i][1], aF[i][2], aF[i][3], bh[0], bh[1]);
                    mma_f16(acc[i][2 * p + 1], aF[i][0], aF[i][1], aF[i][2], aF[i][3], bh[2], bh[3]);
                    mma_f16(acc[i][2 * p],     aF[i][0], aF[i][1], aF[i][2], aF[i][3], bl[0], bl[1]);
                    mma_f16(acc[i][2 * p + 1], aF[i][0], aF[i][1], aF[i][2], aF[i][3], bl[2], bl[3]);
                }
            }
        }
        __syncthreads();
    }

    // epilogue
#pragma unroll
    for (int i = 0; i < 2; i++) {
#pragma unroll
        for (int j = 0; j < 8; j++) {
            int row = m0 + wm * 32 + i * 16 + g;
            int col = n0 + wn * 64 + j * 8 + tg * 2;
            float v0 = acc[i][j][0], v1 = acc[i][j][1];
            float v2 = acc[i][j][2], v3 = acc[i][j][3];
            if (MODE == 0) {
                if (z == 0) {       // Q: fold softmax scale + log2(e)
                    v0 *= QSCALE; v1 *= QSCALE; v2 *= QSCALE; v3 *= QSCALE;
                    *(uint32_t*)&g_qh[(size_t)row * D + col]       = pack_h2(v0, v1);
                    *(uint32_t*)&g_qh[(size_t)(row + 8) * D + col] = pack_h2(v2, v3);
                } else if (z == 1) {
                    *(uint32_t*)&g_kh[(size_t)row * D + col]       = pack_h2(v0, v1);
                    *(uint32_t*)&g_kh[(size_t)(row + 8) * D + col] = pack_h2(v2, v3);
                } else {
                    *(uint32_t*)&g_vh[(size_t)row * D + col]       = pack_h2(v0, v1);
                    *(uint32_t*)&g_vh[(size_t)(row + 8) * D + col] = pack_h2(v2, v3);
                }
            } else {
                float b0 = bias[col], b1 = bias[col + 1];
                *(float2*)&outp[(size_t)row * D + col]       = make_float2(v0 + b0, v1 + b1);
                *(float2*)&outp[(size_t)(row + 8) * D + col] = make_float2(v2 + b0, v3 + b1);
            }
        }
    }
}

// ---------------- FlashAttention-2 with mma.sync fp16 ----------------------
#define APITCH  144
#define AQ_B    (128 * APITCH)          // 18432
#define AKV_B   (64 * APITCH)           // 9216
#define ASTAGE  (2 * AKV_B)             // 18432
#define ASMEM   (AQ_B + 2 * ASTAGE)     // 55296

__global__ void __launch_bounds__(256, 2) attn_mma()
{
    extern __shared__ char sm[];
    const uint32_t smb = smem_u32(sm);
    const int tid = threadIdx.x, wid = tid >> 5, lane = tid & 31;
    const int g = lane >> 2, tg = lane & 3;
    const int mb = blockIdx.x, h = blockIdx.y, b = blockIdx.z;
    const int m0 = mb * 128, bS = b * SEQ;
    const int nt = 2 * mb + 2;

    const uint32_t aoff = (uint32_t)((lane & 7) + ((lane >> 3) & 1) * 8) * APITCH
                        + ((lane >> 4) & 1) * 16;
    const uint32_t boff = (uint32_t)((lane & 7) + ((lane >> 4) & 1) * 8) * APITCH
                        + ((lane >> 3) & 1) * 16;

    const __half* Qg = g_qh + (size_t)(bS + m0) * D + h * 64;
    const __half* Kg = g_kh + (size_t)bS * D + h * 64;
    const __half* Vg = g_vh + (size_t)bS * D + h * 64;

    auto load_tile = [&](int kt, int st) {
        int n0 = kt * 64;
#pragma unroll
        for (int i = 0; i < 2; i++) {
            int idx = tid + i * 256;
            int rid = idx >> 3, c = idx & 7;
            cp16(smb + AQ_B + st * ASTAGE + rid * APITCH + c * 16,
                 Kg + (size_t)(n0 + rid) * D + c * 8);
            cp16(smb + AQ_B + st * ASTAGE + AKV_B + rid * APITCH + c * 16,
                 Vg + (size_t)(n0 + rid) * D + c * 8);
        }
    };

#pragma unroll
    for (int i = 0; i < 4; i++) {
        int idx = tid + i * 256;
        int rid = idx >> 3, c = idx & 7;
        cp16(smb + rid * APITCH + c * 16, Qg + (size_t)rid * D + c * 8);
    }
    load_tile(0, 0); CP_COMMIT();
    load_tile(1, 1); CP_COMMIT(); CP_WAIT1();
    __syncthreads();

    uint32_t qf[4][4];
    {
        uint32_t qbase = smb + (uint32_t)(wid * 16) * APITCH + aoff;
#pragma unroll
        for (int ks = 0; ks < 4; ks++) ldsm4(qf[ks], qbase + ks * 32);
    }

    float oacc[8][4];
#pragma unroll
    for (int j = 0; j < 8; j++)
#pragma unroll
        for (int c = 0; c < 4; c++) oacc[j][c] = 0.f;
    float mp0 = -1e30f, mp1 = -1e30f, lsum0 = 0.f, lsum1 = 0.f;

    const int r0 = m0 + wid * 16 + g;
    const int r1 = r0 + 8;

    for (int kt = 0; kt < nt; kt++) {
        const int st = kt & 1;
        const uint32_t kb = smb + AQ_B + st * ASTAGE;
        const uint32_t vb = kb + AKV_B;

        float s[8][4];
#pragma unroll
        for (int j = 0; j < 8; j++)
#pragma unroll
            for (int c = 0; c < 4; c++) s[j][c] = 0.f;

#pragma unroll
        for (int ks = 0; ks < 4; ks++) {
#pragma unroll
            for (int p = 0; p < 4; p++) {
                uint32_t kf[4];
                ldsm4(kf, kb + (uint32_t)(p * 16) * APITCH + ks * 32 + boff);
                mma_f16(s[2 * p],     qf[ks][0], qf[ks][1], qf[ks][2], qf[ks][3], kf[0], kf[1]);
                mma_f16(s[2 * p + 1], qf[ks][0], qf[ks][1], qf[ks][2], qf[ks][3], kf[2], kf[3]);
            }
        }

        const int n0k = kt * 64;
        if (n0k + 63 > r0) {
#pragma unroll
            for (int j = 0; j < 8; j++) {
                int c0 = n0k + j * 8 + tg * 2;
                if (c0 > r0)     s[j][0] = -1e30f;
                if (c0 + 1 > r0) s[j][1] = -1e30f;
                if (c0 > r1)     s[j][2] = -1e30f;
                if (c0 + 1 > r1) s[j][3] = -1e30f;
            }
        }

        float mx0 = -1e30f, mx1 = -1e30f;
#pragma unroll
        for (int j = 0; j < 8; j++) {
            mx0 = fmaxf(mx0, fmaxf(s[j][0], s[j][1]));
            mx1 = fmaxf(mx1, fmaxf(s[j][2], s[j][3]));
        }
        mx0 = fmaxf(mx0, __shfl_xor_sync(0xffffffffu, mx0, 1));
        mx0 = fmaxf(mx0, __shfl_xor_sync(0xffffffffu, mx0, 2));
        mx1 = fmaxf(mx1, __shfl_xor_sync(0xffffffffu, mx1, 1));
        mx1 = fmaxf(mx1, __shfl_xor_sync(0xffffffffu, mx1, 2));
        float mn0 = fmaxf(mp0, mx0), mn1 = fmaxf(mp1, mx1);
        float al0 = exp2f(mp0 - mn0), al1 = exp2f(mp1 - mn1);
        mp0 = mn0; mp1 = mn1;
        float sum0 = 0.f, sum1 = 0.f;
#pragma unroll
        for (int j = 0; j < 8; j++) {
            s[j][0] = exp2f(s[j][0] - mn0);
            s[j][1] = exp2f(s[j][1] - mn0);
            s[j][2] = exp2f(s[j][2] - mn1);
            s[j][3] = exp2f(s[j][3] - mn1);
            sum0 += s[j][0] + s[j][1];
            sum1 += s[j][2] + s[j][3];
        }
        lsum0 = lsum0 * al0 + sum0;
        lsum1 = lsum1 * al1 + sum1;
#pragma unroll
        for (int j = 0; j < 8; j++) {
            oacc[j][0] *= al0; oacc[j][1] *= al0;
            oacc[j][2] *= al1; oacc[j][3] *= al1;
        }

#pragma unroll
        for (int ks = 0; ks < 4; ks++) {
            uint32_t a0 = pack_h2(s[2 * ks][0],     s[2 * ks][1]);
            uint32_t a1 = pack_h2(s[2 * ks][2],     s[2 * ks][3]);
            uint32_t a2 = pack_h2(s[2 * ks + 1][0], s[2 * ks + 1][1]);
            uint32_t a3 = pack_h2(s[2 * ks + 1][2], s[2 * ks + 1][3]);
#pragma unroll
            for (int p = 0; p < 4; p++) {
                uint32_t vf[4];
                ldsm4t(vf, vb + (uint32_t)(ks * 16) * APITCH + p * 32 + aoff);
                mma_f16(oacc[2 * p],     a0, a1, a2, a3, vf[0], vf[1]);
                mma_f16(oacc[2 * p + 1], a0, a1, a2, a3, vf[2], vf[3]);
            }
        }

        if (kt + 1 >= nt) break;
        __syncthreads();
        if (kt + 2 < nt) { load_tile(kt + 2, st); CP_COMMIT(); CP_WAIT1(); }
        else             { CP_WAIT0(); }
        __syncthreads();
    }

    lsum0 += __shfl_xor_sync(0xffffffffu, lsum0, 1);
    lsum0 += __shfl_xor_sync(0xffffffffu, lsum0, 2);
    lsum1 += __shfl_xor_sync(0xffffffffu, lsum1, 1);
    lsum1 += __shfl_xor_sync(0xffffffffu, lsum1, 2);
    float inv0 = 1.f / lsum0, inv1 = 1.f / lsum1;

    // write ctx directly as fp16 (feeds the out-proj GEMM)
    __half* base0 = g_cth + (size_t)(bS + m0 + wid * 16 + g) * D + h * 64;
#pragma unroll
    for (int jn = 0; jn < 8; jn++) {
        int off = jn * 8 + tg * 2;
        *(uint32_t*)(base0 + off) = pack_h2(oacc[jn][0] * inv0, oacc[jn][1] * inv0);
        *(uint32_t*)(base0 + (size_t)8 * D + off) =
            pack_h2(oacc[jn][2] * inv1, oacc[jn][3] * inv1);
    }
}

// ---------------------------------------------------------------------------
extern "C" void kernel_launch(void* const* d_in, const int* in_sizes, int n_in,
                              void* d_out, int out_size)
{
    const float* x  = (const float*)d_in[0];
    const float* Wq = (const float*)d_in[1];
    const float* Wk = (const float*)d_in[2];
    const float* Wv = (const float*)d_in[3];
    const float* Wo = (const float*)d_in[4];
    const float* bo = (const float*)d_in[5];
    float* out = (float*)d_out;

    static bool attr_set = false;
    if (!attr_set) {
        cudaFuncSetAttribute(gemm_mma<0>, cudaFuncAttributeMaxDynamicSharedMemorySize, GSMEM);
        cudaFuncSetAttribute(gemm_mma<1>, cudaFuncAttributeMaxDynamicSharedMemorySize, GSMEM);
        cudaFuncSetAttribute(attn_mma,    cudaFuncAttributeMaxDynamicSharedMemorySize, ASMEM);
        attr_set = true;
    }

    __half* xf;
    cudaGetSymbolAddress((void**)&xf, g_xf);

    conv_x<<<(MTOT * D / 4) / 256, 256>>>(x, xf);
    conv_w<<<dim3(32, 32, 4), dim3(32, 8)>>>(Wq, Wk, Wv, Wo);
    gemm_mma<0><<<dim3(8, 64, 3), 256, GSMEM>>>(nullptr, nullptr);
    attn_mma<<<dim3(SEQ / 128, NHEAD, BATCH), 256, ASMEM>>>();
    gemm_mma<1><<<dim3(8, 64, 1), 256, GSMEM>>>(out, bo);
}